// round 11
// baseline (speedup 1.0000x reference)
#include <cuda_runtime.h>

static constexpr int B = 256;
static constexpr int S = 2048;
static constexpr int T = 48;

typedef unsigned long long u64;

// cross-kernel scratch (static __device__: allowed, no dynamic alloc)
__device__ float g_dir[B][2][48];   // [batch][0=alpha_1023 dir, 1=beta_1024 dir]
__device__ float g_c[B][11];        // per-chain log-scales: fw 0..5, bw 6..10

// ---- packed f32x2 helpers (Blackwell FFMA2: only reachable via PTX) ----
__device__ __forceinline__ u64 pack2(float x, float y) {
    u64 r; asm("mov.b64 %0, {%1, %2};" : "=l"(r) : "f"(x), "f"(y)); return r;
}
__device__ __forceinline__ void unpack2(u64 v, float& x, float& y) {
    asm("mov.b64 {%0, %1}, %2;" : "=f"(x), "=f"(y) : "l"(v));
}
__device__ __forceinline__ u64 ffma2(u64 a, u64 b, u64 c) {
    u64 d; asm("fma.rn.f32x2 %0, %1, %2, %3;" : "=l"(d) : "l"(a), "l"(b), "l"(c)); return d;
}
__device__ __forceinline__ u64 fadd2(u64 a, u64 b) {
    u64 d; asm("add.rn.f32x2 %0, %1, %2;" : "=l"(d) : "l"(a), "l"(b)); return d;
}

// TWO same-direction scaled-exp-domain semiring chains per warp, sharing the
// E register constants (E is batch/segment independent!). Transposed pair
// packing (R7 body). Lane l owns states (2l,2l+1); lanes 24..31 padding.
// niterX/resetX/epX RUNTIME -> ONE inlined instance per BW (R5 lesson).
// Mixed-length pairs: guarded 8-step tail (warp-uniform guards).
// resetX >= 0: lane0-normalize there, zero scale (PF stitch boundary).
template<int BW>
__device__ __forceinline__ void run_chain2(
    const float* __restrict__ ePA, const float* __restrict__ ePB,
    const u64 (&EA)[24], const u64 (&EB)[24],
    float pAx, float pAy, float pBx, float pBy,
    int niterA, int niterB, int resetA, int resetB, int lane,
    float2 (*bufA)[32], float2 (*bufB)[32],
    float* rA, float* rB)            // out: {px, py, c}
{
    int cexpA = 0, cexpB = 0;
    float2 ebA[4], ebB[4];
    int cb = 0;

#define E_OFF(i) ( BW ? (size_t)(S - 1 - (i)) * T : (size_t)((i) + 1) * T )

#pragma unroll
    for (int u = 0; u < 4; ++u) {
        ebA[u] = *(const float2*)(ePA + E_OFF(u));
        ebB[u] = *(const float2*)(ePB + E_OFF(u));
    }

#define MATVEC2(bufX, fex, fey, px, py) do {                               \
    u64 a0=0ull,a1=0ull,a2=0ull,a3=0ull,a4=0ull,a5=0ull,a6=0ull,a7=0ull;   \
    const float4* bv = (const float4*)bufX[cb];                            \
    _Pragma("unroll")                                                      \
    for (int m = 0; m < 12; m += 4) {                                      \
        float4 v0 = bv[m];                                                 \
        u64 b0 = pack2(v0.x, v0.y), b1 = pack2(v0.z, v0.w);                \
        a0 = ffma2(EA[2*m  ], b0, a0);  a4 = ffma2(EB[2*m  ], b0, a4);     \
        a1 = ffma2(EA[2*m+1], b1, a1);  a5 = ffma2(EB[2*m+1], b1, a5);     \
        float4 v1 = bv[m+1];                                               \
        u64 b2 = pack2(v1.x, v1.y), b3 = pack2(v1.z, v1.w);                \
        a2 = ffma2(EA[2*m+2], b2, a2);  a6 = ffma2(EB[2*m+2], b2, a6);     \
        a3 = ffma2(EA[2*m+3], b3, a3);  a7 = ffma2(EB[2*m+3], b3, a7);     \
        float4 v2 = bv[m+2];                                               \
        u64 b4 = pack2(v2.x, v2.y), b5 = pack2(v2.z, v2.w);                \
        a0 = ffma2(EA[2*m+4], b4, a0);  a4 = ffma2(EB[2*m+4], b4, a4);     \
        a1 = ffma2(EA[2*m+5], b5, a1);  a5 = ffma2(EB[2*m+5], b5, a5);     \
        float4 v3 = bv[m+3];                                               \
        u64 b6 = pack2(v3.x, v3.y), b7 = pack2(v3.z, v3.w);                \
        a2 = ffma2(EA[2*m+6], b6, a2);  a6 = ffma2(EB[2*m+6], b6, a6);     \
        a3 = ffma2(EA[2*m+7], b7, a3);  a7 = ffma2(EB[2*m+7], b7, a7);     \
    }                                                                      \
    u64 q0 = fadd2(fadd2(a0, a1), fadd2(a2, a3));                          \
    u64 q1 = fadd2(fadd2(a4, a5), fadd2(a6, a7));                          \
    float x0, y0; unpack2(q0, x0, y0);                                     \
    float x1, y1; unpack2(q1, x1, y1);                                     \
    float n0 = x0 + y0, n1 = x1 + y1;                                      \
    px = BW ? n0 : n0 * (fex);                                             \
    py = BW ? n1 : n1 * (fey);                                             \
} while (0)

#define RENORM1(px, py, cexp, reset_i, i) do {                             \
    float ref = __shfl_sync(0xffffffffu, px, 0);                           \
    if ((i) == (reset_i)) {                                                \
        float inv = __fdividef(1.f, ref);                                  \
        px *= inv; py *= inv;                                              \
        cexp = 0;                           /* stitch boundary: discard */ \
    } else {                                                               \
        int ex = (__float_as_int(ref) >> 23) & 255;                        \
        float sc = __int_as_float((254 - ex) << 23);   /* 2^(127-ex) */    \
        px *= sc; py *= sc;                                                \
        cexp += ex - 127;                                                  \
    }                                                                      \
} while (0)

#define BODY2(i, u, RN, ACTA, ACTB) do {                                   \
    float fexA, feyA, fexB, feyB;                                          \
    if (ACTA) {                                                            \
        float2 e = ebA[(u) & 3]; int tn = (i) + 4;                         \
        if (tn < niterA) ebA[(u) & 3] = *(const float2*)(ePA + E_OFF(tn)); \
        fexA = __expf(e.x); feyA = __expf(e.y);                            \
        bufA[cb][lane] = make_float2(BW ? pAx * fexA : pAx,                \
                                     BW ? pAy * feyA : pAy);               \
    }                                                                      \
    if (ACTB) {                                                            \
        float2 e = ebB[(u) & 3]; int tn = (i) + 4;                         \
        if (tn < niterB) ebB[(u) & 3] = *(const float2*)(ePB + E_OFF(tn)); \
        fexB = __expf(e.x); feyB = __expf(e.y);                            \
        bufB[cb][lane] = make_float2(BW ? pBx * fexB : pBx,                \
                                     BW ? pBy * feyB : pBy);               \
    }                                                                      \
    __syncwarp();                                                          \
    if (ACTA) MATVEC2(bufA, fexA, feyA, pAx, pAy);                         \
    if (ACTB) MATVEC2(bufB, fexB, feyB, pBx, pBy);                         \
    cb ^= 1;                                                               \
    if (RN) {                                                              \
        RENORM1(pAx, pAy, cexpA, resetA, i);                               \
        RENORM1(pBx, pBy, cexpB, resetB, i);                               \
    }                                                                      \
} while (0)

    const int nmin  = niterA < niterB ? niterA : niterB;
    const int nmain = nmin & ~7;                 // resets (i=23) < nmain always
    for (int i = 0; i < nmain; i += 8) {
#pragma unroll
        for (int u = 0; u < 8; ++u) BODY2(i + u, u, (u == 7), true, true);
    }
    // guarded tail (max(niterA,niterB) <= nmain+8 by construction)
#pragma unroll
    for (int u = 0; u < 8; ++u) {
        int i = nmain + u;
        BODY2(i, u, false, i < niterA, i < niterB);
    }

    // final exact renorm (lane0-normalize) + exact log of scale
    float cA = (float)cexpA * 0.69314718055994531f;
    float cB = (float)cexpB * 0.69314718055994531f;
    {
        float ref = __shfl_sync(0xffffffffu, pAx, 0);
        float inv = __fdividef(1.f, ref);
        pAx *= inv; pAy *= inv; cA += __logf(ref);
    }
    {
        float ref = __shfl_sync(0xffffffffu, pBx, 0);
        float inv = __fdividef(1.f, ref);
        pBx *= inv; pBy *= inv; cB += __logf(ref);
    }
    rA[0] = pAx; rA[1] = pAy; rA[2] = cA;
    rB[0] = pBx; rB[1] = pBy; rB[2] = cB;
#undef BODY2
#undef RENORM1
#undef MATVEC2
#undef E_OFF
}

// PF 11-way split per batch (6 fw + 5 bw), burn-in 24.
// fw trusted: seg0 t=1..188 (exact, niter 188); seg s>=1: 167 each,
//   off = 164+(s-1)*167, niter 191, reset i=23. seg5 ends t=1023 -> dir alpha.
// bw trusted: seg0 e=2047..1824 (exact); seg s>=1: 200 each,
//   ep = ep0 - 200*s*T, niter 224, reset i=23. seg4 ends e=1024 -> dir beta.
// Warps: global W = blockIdx*2 + w. W<768: fw pair (chains 2W,2W+1; chain
// c -> b=c/6, seg=c%6). Else bw pair (Q=W-768; chain c=2Q..: b=c/5, seg=c%5;
// pairs may cross batches - E is batch-independent).
__global__ void __launch_bounds__(64, 5)
crf_chains(const float* __restrict__ emis,
           const float* __restrict__ trans,
           const float* __restrict__ startT,
           const float* __restrict__ endT)
{
    __shared__ __align__(16) float2 bufs[2][2][2][32]; // [warp][chain][db][lane]

    const int tid = threadIdx.x;
    const int w   = tid >> 5;
    const int l   = tid & 31;
    const bool act = l < 24;
    const int j0 = act ? 2*l     : 0;
    const int j1 = act ? 2*l + 1 : 0;

    const int  W    = blockIdx.x * 2 + w;
    const bool isFw = (W < 768);

    // per-lane exp(transition) pair constants (96 regs), transposed packing
    u64 EA[24], EB[24];
    if (isFw) {
#pragma unroll
        for (int k = 0; k < 24; ++k) {
            float a0 = __expf(trans[(2*k)*T   + j0]);
            float a1 = __expf(trans[(2*k+1)*T + j0]);
            float b0 = __expf(trans[(2*k)*T   + j1]);
            float b1 = __expf(trans[(2*k+1)*T + j1]);
            EA[k] = act ? pack2(a0, a1) : 0ull;
            EB[k] = act ? pack2(b0, b1) : 0ull;
        }
    } else {
#pragma unroll
        for (int k = 0; k < 24; ++k) {
            float a0 = __expf(trans[j0*T + 2*k]);
            float a1 = __expf(trans[j0*T + 2*k+1]);
            float b0 = __expf(trans[j1*T + 2*k]);
            float b1 = __expf(trans[j1*T + 2*k+1]);
            EA[k] = act ? pack2(a0, a1) : 0ull;
            EB[k] = act ? pack2(b0, b1) : 0ull;
        }
    }

    // chain identities
    int cA, cB, bA, segA, bB, segB;
    if (isFw) { cA = 2*W;         cB = cA + 1; bA = cA/6; segA = cA%6; bB = cB/6; segB = cB%6; }
    else      { cA = 2*(W - 768); cB = cA + 1; bA = cA/5; segA = cA%5; bB = cB/5; segB = cB%5; }

    // per-chain runtime parameters
    const float *epA, *epB;
    int nA, nB, rsA, rsB;
    float p0Ax, p0Ay, p0Bx, p0By;
    {
        const float* e0A = emis + (size_t)bA * S * T + j0;
        const float* e0B = emis + (size_t)bB * S * T + j0;
        if (isFw) {
            int offA = (segA == 0) ? 0 : 164 + (segA - 1) * 167;
            int offB = (segB == 0) ? 0 : 164 + (segB - 1) * 167;
            epA = e0A + (size_t)offA * T;  epB = e0B + (size_t)offB * T;
            nA = (segA == 0) ? 188 : 191;  nB = (segB == 0) ? 188 : 191;
            rsA = (segA == 0) ? -1 : 23;   rsB = (segB == 0) ? -1 : 23;
            if (segA == 0) { float2 e0 = *(const float2*)e0A;
                p0Ax = act ? __expf(startT[j0] + e0.x) : 0.f;
                p0Ay = act ? __expf(startT[j1] + e0.y) : 0.f;
            } else { p0Ax = act ? 1.f : 0.f; p0Ay = p0Ax; }
            if (segB == 0) { float2 e0 = *(const float2*)e0B;
                p0Bx = act ? __expf(startT[j0] + e0.x) : 0.f;
                p0By = act ? __expf(startT[j1] + e0.y) : 0.f;
            } else { p0Bx = act ? 1.f : 0.f; p0By = p0Bx; }
        } else {
            epA = e0A - (size_t)(200 * segA) * T;
            epB = e0B - (size_t)(200 * segB) * T;
            nA = 224; nB = 224;
            rsA = segA ? 23 : -1;  rsB = segB ? 23 : -1;
            if (segA == 0) {
                p0Ax = act ? __expf(endT[j0]) : 0.f;
                p0Ay = act ? __expf(endT[j1]) : 0.f;
            } else { p0Ax = act ? 1.f : 0.f; p0Ay = p0Ax; }
            if (segB == 0) {
                p0Bx = act ? __expf(endT[j0]) : 0.f;
                p0By = act ? __expf(endT[j1]) : 0.f;
            } else { p0Bx = act ? 1.f : 0.f; p0By = p0Bx; }
        }
    }

    float rA[3], rB[3];
    if (isFw)
        run_chain2<0>(epA, epB, EA, EB, p0Ax, p0Ay, p0Bx, p0By,
                      nA, nB, rsA, rsB, l, bufs[w][0], bufs[w][1], rA, rB);
    else
        run_chain2<1>(epA, epB, EA, EB, p0Ax, p0Ay, p0Bx, p0By,
                      nA, nB, rsA, rsB, l, bufs[w][0], bufs[w][1], rA, rB);

    // boundary direction vectors + scales
    if (act) {
        if (isFw) {
            if (segA == 5) { g_dir[bA][0][2*l] = rA[0]; g_dir[bA][0][2*l+1] = rA[1]; }
            if (segB == 5) { g_dir[bB][0][2*l] = rB[0]; g_dir[bB][0][2*l+1] = rB[1]; }
        } else {
            if (segA == 4) { g_dir[bA][1][2*l] = rA[0]; g_dir[bA][1][2*l+1] = rA[1]; }
            if (segB == 4) { g_dir[bB][1][2*l] = rB[0]; g_dir[bB][1][2*l+1] = rB[1]; }
        }
    }
    if (l == 0) {
        g_c[bA][isFw ? segA : 6 + segA] = rA[2];
        g_c[bB][isFw ? segB : 6 + segB] = rB[2];
    }
}

// Kernel 2: combine + numerator, 256 threads for gather parallelism.
__global__ void __launch_bounds__(256)
crf_combine(const float* __restrict__ emis,
            const int*   __restrict__ tagsw,   // int32 view; int64 auto-detected
            const int*   __restrict__ mask,
            const float* __restrict__ trans,
            const float* __restrict__ startT,
            const float* __restrict__ endT,
            float* __restrict__ out)
{
    __shared__ float shA[8], shB[8];
    const int b   = blockIdx.x;
    const int tid = threadIdx.x;
    const int wp  = tid >> 5;
    const int l   = tid & 31;
    const size_t base = (size_t)b * S * T;

    // dot(dir_alpha, dir_beta): warp-tree reduce
    float v = (tid < 48) ? g_dir[b][0][tid] * g_dir[b][1][tid] : 0.f;
#pragma unroll
    for (int d = 16; d; d >>= 1) v += __shfl_xor_sync(0xffffffffu, v, d);
    if (l == 0) shA[wp] = v;

    // ---- tags dtype detection: int64 iff sampled odd 32-bit words all zero ----
    int oddw = tagsw[2*tid + 1];
    int any  = __syncthreads_or(oddw != 0);
    const bool is64 = (any == 0);

    // ---- numerator: gold-path score (8 gathers/thread, MLP-rich) ----
    const size_t tbase = (size_t)b * S;
    float num = 0.f;
#pragma unroll
    for (int k = 0; k < 8; ++k) {
        int s = tid + 256*k;
        int cur = is64 ? tagsw[(tbase + s) * 2] : tagsw[tbase + s];
        if (s == 0) {
            num += startT[cur] + emis[base + cur];
        } else {
            int prev = is64 ? tagsw[(tbase + s - 1) * 2] : tagsw[tbase + s - 1];
            float m = (float)mask[tbase + s];
            num += (trans[prev*T + cur] + emis[base + (size_t)s*T + cur]) * m;
        }
        if (s == S - 1) num += endT[cur];
    }
#pragma unroll
    for (int d = 16; d; d >>= 1) num += __shfl_xor_sync(0xffffffffu, num, d);
    if (l == 0) shB[wp] = num;
    __syncthreads();

    if (tid == 0) {
        float dot = 0.f, nm = 0.f;
#pragma unroll
        for (int k = 0; k < 8; ++k) { dot += shA[k]; nm += shB[k]; }
        float cs = 0.f;
#pragma unroll
        for (int k = 0; k < 11; ++k) cs += g_c[b][k];
        out[b] = __logf(dot) + cs - nm;              // NLL
    }
}

extern "C" void kernel_launch(void* const* d_in, const int* in_sizes, int n_in,
                              void* d_out, int out_size) {
    (void)in_sizes; (void)n_in; (void)out_size;
    const float* emis   = (const float*)d_in[0];
    const int*   tagsw  = (const int*)  d_in[1];
    const int*   mask   = (const int*)  d_in[2];
    const float* trans  = (const float*)d_in[3];
    const float* startT = (const float*)d_in[4];
    const float* endT   = (const float*)d_in[5];
    crf_chains <<<704, 64>>>(emis, trans, startT, endT);
    crf_combine<<<B, 256>>>(emis, tagsw, mask, trans, startT, endT, (float*)d_out);
}

// round 13
// speedup vs baseline: 1.2308x; 1.2308x over previous
#include <cuda_runtime.h>

static constexpr int B = 256;
static constexpr int S = 2048;
static constexpr int T = 48;

typedef unsigned long long u64;

// ---- packed f32x2 helpers (Blackwell FFMA2: only reachable via PTX) ----
__device__ __forceinline__ u64 pack2(float x, float y) {
    u64 r; asm("mov.b64 %0, {%1, %2};" : "=l"(r) : "f"(x), "f"(y)); return r;
}
__device__ __forceinline__ void unpack2(u64 v, float& x, float& y) {
    asm("mov.b64 {%0, %1}, %2;" : "=f"(x), "=f"(y) : "l"(v));
}
__device__ __forceinline__ u64 ffma2(u64 a, u64 b, u64 c) {
    u64 d; asm("fma.rn.f32x2 %0, %1, %2, %3;" : "=l"(d) : "l"(a), "l"(b), "l"(c)); return d;
}
__device__ __forceinline__ u64 fadd2(u64 a, u64 b) {
    u64 d; asm("add.rn.f32x2 %0, %1, %2;" : "=l"(d) : "l"(a), "l"(b)); return d;
}

// One scaled-exp-domain semiring chain with transposed pair packing:
// output j0 accumulates over source pairs; b-operand is lane k's natural
// (sx,sy) float2 -> 1 STS.64 + 12 broadcast LDS.128 per step.
// BW=0: alpha forward (matvec then *exp(e)). BW=1: beta backward (*exp(e)
// then matvec). Lane l owns states (2l,2l+1); lanes 24..31 padding (E pairs
// zero -> state identically 0; their buf slots never read).
// niter / reset_i / ep are RUNTIME so each BW direction inlines exactly ONCE
// (multiple compile-time instances destroy prefetch pipelining - R5 lesson).
// reset_i >= 0: lane0-normalize there and zero scale (PF stitch boundary).
// CONSTRAINT: reset_i % 8 == 7 (renorm only runs at u==7) - R12's bug.
template<int BW>
__device__ __forceinline__ void run_chain(
    const float* __restrict__ ep,    // adjusted emission base (+ j0)
    const u64 (&EA)[24], const u64 (&EB)[24],
    float px, float py, int niter, int reset_i, int lane,
    float2 (*buf)[32],               // per-warp double buffer [2][32]
    float& pxOut, float& pyOut, float& cOut)
{
    int cexp = 0;                    // accumulated power-of-two scale
    float2 ebuf[8];
    int cb = 0;

#define E_OFF(i) ( BW ? (size_t)(S - 1 - (i)) * T : (size_t)((i) + 1) * T )

#pragma unroll
    for (int u = 0; u < 8; ++u)
        ebuf[u] = *(const float2*)(ep + E_OFF(u));   // niter >= 357 always

#define BODY(i, u, RENORM) do {                                            \
    float2 e = ebuf[u];                                                    \
    int tn = (i) + 8;                                                      \
    if (tn < niter) ebuf[u] = *(const float2*)(ep + E_OFF(tn));            \
    float fex = __expf(e.x);                                               \
    float fey = __expf(e.y);                                               \
    float sx = BW ? px * fex : px;                                         \
    float sy = BW ? py * fey : py;                                         \
    buf[cb][lane] = make_float2(sx, sy);                                   \
    __syncwarp();                                                          \
    u64 a0=0ull,a1=0ull,a2=0ull,a3=0ull,a4=0ull,a5=0ull,a6=0ull,a7=0ull;   \
    const float4* bv = (const float4*)buf[cb];                             \
    _Pragma("unroll")                                                      \
    for (int m = 0; m < 12; m += 4) {                                      \
        float4 v0 = bv[m];                                                 \
        u64 b0 = pack2(v0.x, v0.y), b1 = pack2(v0.z, v0.w);                \
        a0 = ffma2(EA[2*m  ], b0, a0);  a4 = ffma2(EB[2*m  ], b0, a4);     \
        a1 = ffma2(EA[2*m+1], b1, a1);  a5 = ffma2(EB[2*m+1], b1, a5);     \
        float4 v1 = bv[m+1];                                               \
        u64 b2 = pack2(v1.x, v1.y), b3 = pack2(v1.z, v1.w);                \
        a2 = ffma2(EA[2*m+2], b2, a2);  a6 = ffma2(EB[2*m+2], b2, a6);     \
        a3 = ffma2(EA[2*m+3], b3, a3);  a7 = ffma2(EB[2*m+3], b3, a7);     \
        float4 v2 = bv[m+2];                                               \
        u64 b4 = pack2(v2.x, v2.y), b5 = pack2(v2.z, v2.w);                \
        a0 = ffma2(EA[2*m+4], b4, a0);  a4 = ffma2(EB[2*m+4], b4, a4);     \
        a1 = ffma2(EA[2*m+5], b5, a1);  a5 = ffma2(EB[2*m+5], b5, a5);     \
        float4 v3 = bv[m+3];                                               \
        u64 b6 = pack2(v3.x, v3.y), b7 = pack2(v3.z, v3.w);                \
        a2 = ffma2(EA[2*m+6], b6, a2);  a6 = ffma2(EB[2*m+6], b6, a6);     \
        a3 = ffma2(EA[2*m+7], b7, a3);  a7 = ffma2(EB[2*m+7], b7, a7);     \
    }                                                                      \
    u64 q0 = fadd2(fadd2(a0, a1), fadd2(a2, a3));                          \
    u64 q1 = fadd2(fadd2(a4, a5), fadd2(a6, a7));                          \
    float x0, y0; unpack2(q0, x0, y0);                                     \
    float x1, y1; unpack2(q1, x1, y1);                                     \
    float n0 = x0 + y0, n1 = x1 + y1;                                      \
    px = BW ? n0 : n0 * fex;                                               \
    py = BW ? n1 : n1 * fey;                                               \
    cb ^= 1;                                                               \
    if (RENORM) {                                                          \
        float ref = __shfl_sync(0xffffffffu, px, 0);                       \
        if ((i) == reset_i) {                                              \
            float inv = __fdividef(1.f, ref);                              \
            px *= inv; py *= inv;                                          \
            cexp = 0;                       /* stitch boundary: discard */ \
        } else {                                                           \
            int ex = (__float_as_int(ref) >> 23) & 255;                    \
            float sc = __int_as_float((254 - ex) << 23); /* 2^(127-ex) */  \
            px *= sc; py *= sc;                                            \
            cexp += ex - 127;                                              \
        }                                                                  \
    }                                                                      \
} while (0)

    int nmain = niter & ~7;
    for (int i = 0; i < nmain; i += 8) {
#pragma unroll
        for (int u = 0; u < 8; ++u) BODY(i + u, u, (u == 7));
    }
#pragma unroll
    for (int u = 0; u < 8; ++u)
        if (nmain + u < niter) BODY(nmain + u, u, false);

    // final exact renorm (lane0-normalize) + exact log of scale
    float c = (float)cexp * 0.69314718055994531f;
    {
        float ref = __shfl_sync(0xffffffffu, px, 0);
        float inv = __fdividef(1.f, ref);
        px *= inv; py *= inv;
        c += __logf(ref);
    }
    pxOut = px; pyOut = py; cOut = c;
#undef BODY
#undef E_OFF
}

// Perron-Frobenius 6-way split, rebalanced, burn-in 24 (reset i=23, 23%8==7).
//  w0 fw-exact t=1..357                  (357, ep0)        -> c0
//  w1 fw-burn  t=334..690  reset@t=357   (357, ep0+333T)   -> c1
//  w2 fw-burn  t=667..1023 reset@t=690   (357, ep0+666T)   -> dir(alpha_1023)+c2
//  w3 bw-exact e=2047..1690              (358, ep0)        -> c3
//  w4 bw-burn  e=1713..1357 reset@e=1690 (357, ep0-334T)   -> c4
//  w5 bw-burn  e=1380..1024 reset@e=1357 (357, ep0-667T)   -> dir(beta_1024)+c5
// Z = log(dir_alpha . dir_beta) + c0+c1+c2+c3+c4+c5
__global__ void __launch_bounds__(192, 2)
crf_kernel(const float* __restrict__ emis,
           const int*   __restrict__ tagsw,   // int32 view; int64 auto-detected
           const int*   __restrict__ mask,
           const float* __restrict__ trans,
           const float* __restrict__ startT,
           const float* __restrict__ endT,
           float* __restrict__ out)
{
    __shared__ __align__(16) float2 bufs[6][2][32];  // [warp][double-buf][lane]
    __shared__ float shP[48], shR[48], shC[6];
    __shared__ float shRed[192];

    const int b   = blockIdx.x;
    const int tid = threadIdx.x;
    const int w   = tid >> 5;
    const int l   = tid & 31;
    const bool act = l < 24;
    const int j0 = act ? 2*l     : 0;
    const int j1 = act ? 2*l + 1 : 0;

    const size_t base = (size_t)b * S * T;
    const bool fw = (w < 3);

    // per-lane exp(transition) pair constants (96 regs), transposed packing:
    // fw: EA[k]=(E[2k][j0],E[2k+1][j0]), EB[k]=(E[2k][j1],E[2k+1][j1])
    // bw: EA[k]=(E[j0][2k],E[j0][2k+1]), EB[k]=(E[j1][2k],E[j1][2k+1])
    u64 EA[24], EB[24];
    if (fw) {
#pragma unroll
        for (int k = 0; k < 24; ++k) {
            float a0 = __expf(trans[(2*k)*T   + j0]);
            float a1 = __expf(trans[(2*k+1)*T + j0]);
            float b0 = __expf(trans[(2*k)*T   + j1]);
            float b1 = __expf(trans[(2*k+1)*T + j1]);
            EA[k] = act ? pack2(a0, a1) : 0ull;
            EB[k] = act ? pack2(b0, b1) : 0ull;
        }
    } else {
#pragma unroll
        for (int k = 0; k < 24; ++k) {
            float a0 = __expf(trans[j0*T + 2*k]);
            float a1 = __expf(trans[j0*T + 2*k+1]);
            float b0 = __expf(trans[j1*T + 2*k]);
            float b1 = __expf(trans[j1*T + 2*k+1]);
            EA[k] = act ? pack2(a0, a1) : 0ull;
            EB[k] = act ? pack2(b0, b1) : 0ull;
        }
    }

    const float* ep0 = emis + base + j0;

    // runtime per-warp chain parameters (ONE run_chain instance per BW)
    const bool exact = (w == 0) || (w == 3);
    const int  niter = (w == 0) ? 357 : (w == 3) ? 358 : 357;
    const int  reset = exact ? -1 : 23;
    const float* ep =
        (w == 0) ? ep0 :
        (w == 1) ? ep0 + (size_t)333 * T :
        (w == 2) ? ep0 + (size_t)666 * T :
        (w == 3) ? ep0 :
        (w == 4) ? ep0 - (size_t)334 * T :
                   ep0 - (size_t)667 * T;

    float p0x, p0y;
    if (w == 0) {
        float2 e0 = *(const float2*)(ep0);                    // t = 0
        p0x = act ? __expf(startT[j0] + e0.x) : 0.f;
        p0y = act ? __expf(startT[j1] + e0.y) : 0.f;
    } else if (w == 3) {
        p0x = act ? __expf(endT[j0]) : 0.f;
        p0y = act ? __expf(endT[j1]) : 0.f;
    } else {
        p0x = act ? 1.f : 0.f;                                // uniform burn-in
        p0y = act ? 1.f : 0.f;
    }

    float pfx, pfy, cfin;
    if (fw) run_chain<0>(ep, EA, EB, p0x, p0y, niter, reset, l, bufs[w], pfx, pfy, cfin);
    else    run_chain<1>(ep, EA, EB, p0x, p0y, niter, reset, l, bufs[w], pfx, pfy, cfin);

    if (act) {
        if (w == 2) { shP[2*l] = pfx; shP[2*l+1] = pfy; }     // dir(alpha_1023)
        if (w == 5) { shR[2*l] = pfx; shR[2*l+1] = pfy; }     // dir(beta_1024)
    }
    if (l == 0) shC[w] = cfin;
    __syncthreads();

    shRed[tid] = (tid < 48) ? shP[tid] * shR[tid] : 0.f;
    __syncthreads();

    float Z = 0.f;
    if (tid == 0) {
        float dot = 0.f;
#pragma unroll
        for (int k = 0; k < 48; ++k) dot += shRed[k];
        Z = __logf(dot) + shC[0] + shC[1] + shC[2] + shC[3] + shC[4] + shC[5];
    }

    // ---- tags dtype detection: int64 iff sampled odd 32-bit words all zero ----
    int oddw = tagsw[2*tid + 1];
    int any  = __syncthreads_or(oddw != 0);          // also a barrier for shRed reuse
    const bool is64 = (any == 0);

    // ---- numerator: gold-path score ----
    const size_t tbase = (size_t)b * S;
    float num = 0.f;
#pragma unroll 4
    for (int s = tid; s < S; s += 192) {
        int cur = is64 ? tagsw[(tbase + s) * 2] : tagsw[tbase + s];
        if (s == 0) {
            num += startT[cur] + emis[base + cur];
        } else {
            int prev = is64 ? tagsw[(tbase + s - 1) * 2] : tagsw[tbase + s - 1];
            float m = (float)mask[tbase + s];
            num += (trans[prev*T + cur] + emis[base + (size_t)s*T + cur]) * m;
        }
        if (s == S - 1) num += endT[cur];
    }
    shRed[tid] = num;
    __syncthreads();
    if (tid == 0) {
        float tot = 0.f;
#pragma unroll
        for (int k = 0; k < 192; ++k) tot += shRed[k];
        out[b] = Z - tot;                            // NLL
    }
}

extern "C" void kernel_launch(void* const* d_in, const int* in_sizes, int n_in,
                              void* d_out, int out_size) {
    (void)in_sizes; (void)n_in; (void)out_size;
    crf_kernel<<<B, 192>>>(
        (const float*)d_in[0],   // emissions
        (const int*)  d_in[1],   // tags (i32 or i64, detected on device)
        (const int*)  d_in[2],   // mask
        (const float*)d_in[3],   // transitions
        (const float*)d_in[4],   // start_transitions
        (const float*)d_in[5],   // end_transitions
        (float*)d_out);
}

// round 14
// speedup vs baseline: 1.2973x; 1.0540x over previous
#include <cuda_runtime.h>

static constexpr int B = 256;
static constexpr int S = 2048;
static constexpr int T = 48;

typedef unsigned long long u64;

// cross-kernel scratch (static __device__: allowed, no dynamic alloc)
__device__ float g_dir[B][2][48];     // [batch][0=alpha_1023 dir, 1=beta_1024 dir]
__device__ float g_c[B][6];           // per-chain log-scales (seg 0..5)
__device__ float g_numpart[B * 6];    // per-chain numerator partials

// ---- packed f32x2 helpers (Blackwell FFMA2: only reachable via PTX) ----
__device__ __forceinline__ u64 pack2(float x, float y) {
    u64 r; asm("mov.b64 %0, {%1, %2};" : "=l"(r) : "f"(x), "f"(y)); return r;
}
__device__ __forceinline__ void unpack2(u64 v, float& x, float& y) {
    asm("mov.b64 {%0, %1}, %2;" : "=f"(x), "=f"(y) : "l"(v));
}
__device__ __forceinline__ u64 ffma2(u64 a, u64 b, u64 c) {
    u64 d; asm("fma.rn.f32x2 %0, %1, %2, %3;" : "=l"(d) : "l"(a), "l"(b), "l"(c)); return d;
}
__device__ __forceinline__ u64 fadd2(u64 a, u64 b) {
    u64 d; asm("add.rn.f32x2 %0, %1, %2;" : "=l"(d) : "l"(a), "l"(b)); return d;
}

// One scaled-exp-domain semiring chain, transposed pair packing (R7/R13 body).
// BW=0: alpha forward (matvec then *exp(e)); BW=1: beta backward (*exp(e)
// then matvec). Lane l owns states (2l,2l+1); lanes 24..31 padding (E pairs
// zero -> state identically 0; buf slots never read).
// niter/reset_i/ep RUNTIME -> ONE inlined instance per BW (R5 lesson).
// reset_i >= 0: lane0-normalize there, zero scale (PF stitch; reset%8==7!).
// Prefetch is UNGUARDED: all 8-step lookaheads verified in-bounds for the
// segment offsets used below.
template<int BW>
__device__ __forceinline__ void run_chain(
    const float* __restrict__ ep,    // adjusted emission base (+ j0)
    const u64 (&EA)[24], const u64 (&EB)[24],
    float px, float py, int niter, int reset_i, int lane,
    float2 (*buf)[32],               // per-warp double buffer [2][32]
    float& pxOut, float& pyOut, float& cOut)
{
    int cexp = 0;                    // accumulated power-of-two scale
    float2 ebuf[8];
    int cb = 0;

#define E_OFF(i) ( BW ? (size_t)(S - 1 - (i)) * T : (size_t)((i) + 1) * T )

#pragma unroll
    for (int u = 0; u < 8; ++u)
        ebuf[u] = *(const float2*)(ep + E_OFF(u));

#define BODY(i, u, RENORM) do {                                            \
    float2 e = ebuf[u];                                                    \
    ebuf[u] = *(const float2*)(ep + E_OFF((i) + 8));  /* always in-bounds */\
    float fex = __expf(e.x);                                               \
    float fey = __expf(e.y);                                               \
    float sx = BW ? px * fex : px;                                         \
    float sy = BW ? py * fey : py;                                         \
    buf[cb][lane] = make_float2(sx, sy);                                   \
    __syncwarp();                                                          \
    u64 a0=0ull,a1=0ull,a2=0ull,a3=0ull,a4=0ull,a5=0ull,a6=0ull,a7=0ull;   \
    const float4* bv = (const float4*)buf[cb];                             \
    _Pragma("unroll")                                                      \
    for (int m = 0; m < 12; m += 4) {                                      \
        float4 v0 = bv[m];                                                 \
        u64 b0 = pack2(v0.x, v0.y), b1 = pack2(v0.z, v0.w);                \
        a0 = ffma2(EA[2*m  ], b0, a0);  a4 = ffma2(EB[2*m  ], b0, a4);     \
        a1 = ffma2(EA[2*m+1], b1, a1);  a5 = ffma2(EB[2*m+1], b1, a5);     \
        float4 v1 = bv[m+1];                                               \
        u64 b2 = pack2(v1.x, v1.y), b3 = pack2(v1.z, v1.w);                \
        a2 = ffma2(EA[2*m+2], b2, a2);  a6 = ffma2(EB[2*m+2], b2, a6);     \
        a3 = ffma2(EA[2*m+3], b3, a3);  a7 = ffma2(EB[2*m+3], b3, a7);     \
        float4 v2 = bv[m+2];                                               \
        u64 b4 = pack2(v2.x, v2.y), b5 = pack2(v2.z, v2.w);                \
        a0 = ffma2(EA[2*m+4], b4, a0);  a4 = ffma2(EB[2*m+4], b4, a4);     \
        a1 = ffma2(EA[2*m+5], b5, a1);  a5 = ffma2(EB[2*m+5], b5, a5);     \
        float4 v3 = bv[m+3];                                               \
        u64 b6 = pack2(v3.x, v3.y), b7 = pack2(v3.z, v3.w);                \
        a2 = ffma2(EA[2*m+6], b6, a2);  a6 = ffma2(EB[2*m+6], b6, a6);     \
        a3 = ffma2(EA[2*m+7], b7, a3);  a7 = ffma2(EB[2*m+7], b7, a7);     \
    }                                                                      \
    u64 q0 = fadd2(fadd2(a0, a1), fadd2(a2, a3));                          \
    u64 q1 = fadd2(fadd2(a4, a5), fadd2(a6, a7));                          \
    float x0, y0; unpack2(q0, x0, y0);                                     \
    float x1, y1; unpack2(q1, x1, y1);                                     \
    float n0 = x0 + y0, n1 = x1 + y1;                                      \
    px = BW ? n0 : n0 * fex;                                               \
    py = BW ? n1 : n1 * fey;                                               \
    cb ^= 1;                                                               \
    if (RENORM) {                                                          \
        float ref = __shfl_sync(0xffffffffu, px, 0);                       \
        if ((i) == reset_i) {                                              \
            float inv = __fdividef(1.f, ref);                              \
            px *= inv; py *= inv;                                          \
            cexp = 0;                       /* stitch boundary: discard */ \
        } else {                                                           \
            int ex = (__float_as_int(ref) >> 23) & 255;                    \
            float sc = __int_as_float((254 - ex) << 23); /* 2^(127-ex) */  \
            px *= sc; py *= sc;                                            \
            cexp += ex - 127;                                              \
        }                                                                  \
    }                                                                      \
} while (0)

    int nmain = niter & ~7;
    for (int i = 0; i < nmain; i += 8) {
#pragma unroll
        for (int u = 0; u < 8; ++u) BODY(i + u, u, (u == 7));
    }
#pragma unroll
    for (int u = 0; u < 8; ++u)
        if (nmain + u < niter) BODY(nmain + u, u, false);

    // final exact renorm (lane0-normalize) + exact log of scale
    float c = (float)cexp * 0.69314718055994531f;
    {
        float ref = __shfl_sync(0xffffffffu, px, 0);
        float inv = __fdividef(1.f, ref);
        px *= inv; py *= inv;
        c += __logf(ref);
    }
    pxOut = px; pyOut = py; cOut = c;
#undef BODY
#undef E_OFF
}

// Kernel 1: 296 blocks (=2x148: every SM hosts exactly 2 resident blocks via
// the bid%148 placement LUT) x 192 threads. Trailing blocks carry fewer
// ACTIVE warps so no SM exceeds 11 active chain-warps (vs 12/6 imbalance of
// the 256-block layout): blocks 0..147 -> 6 chains, 148..203 -> 5,
// 204..295 -> 4 (total 1536). Idle warps exit immediately; NO __syncthreads.
// Chain C -> batch C/6, seg C%6 (seg 0..2 fw, 3..5 bw).
// Schedule (R13-validated stitch, burn-in 24, reset i=23):
//  fw s0 exact t=1..357 (357);  s1 ep0+333T n357 r23;  s2 ep0+666T n357 r23 -> alpha dir
//  bw s0 exact e=2047..1690 (358); s1 ep0-334T n357 r23; s2 ep0-667T n357 r23 -> beta dir
// Epilogue per warp: numerator partial over s in [seg*2048/6,(seg+1)*2048/6).
__global__ void __launch_bounds__(192, 2)
crf_chains(const float* __restrict__ emis,
           const int*   __restrict__ tagsw,   // int32 view; int64 auto-detected
           const int*   __restrict__ mask,
           const float* __restrict__ trans,
           const float* __restrict__ startT,
           const float* __restrict__ endT)
{
    __shared__ __align__(16) float2 bufs[6][2][32];  // [warp][double-buf][lane]

    const int blk = blockIdx.x;
    const int tid = threadIdx.x;
    const int w   = tid >> 5;
    const int l   = tid & 31;

    int base, count;
    if (blk < 148)      { base = 6 * blk;              count = 6; }
    else if (blk < 204) { base = 888  + 5 * (blk-148); count = 5; }
    else                { base = 1168 + 4 * (blk-204); count = 4; }
    if (w >= count) return;                  // idle warp: free the slot

    const int C   = base + w;                // global chain id
    const int b   = C / 6;
    const int seg = C % 6;
    const bool fw = (seg < 3);
    const int  si = fw ? seg : seg - 3;

    const bool act = l < 24;
    const int j0 = act ? 2*l     : 0;
    const int j1 = act ? 2*l + 1 : 0;

    // per-lane exp(transition) pair constants (96 regs), transposed packing
    u64 EA[24], EB[24];
    if (fw) {
#pragma unroll
        for (int k = 0; k < 24; ++k) {
            float a0 = __expf(trans[(2*k)*T   + j0]);
            float a1 = __expf(trans[(2*k+1)*T + j0]);
            float b0 = __expf(trans[(2*k)*T   + j1]);
            float b1 = __expf(trans[(2*k+1)*T + j1]);
            EA[k] = act ? pack2(a0, a1) : 0ull;
            EB[k] = act ? pack2(b0, b1) : 0ull;
        }
    } else {
#pragma unroll
        for (int k = 0; k < 24; ++k) {
            float a0 = __expf(trans[j0*T + 2*k]);
            float a1 = __expf(trans[j0*T + 2*k+1]);
            float b0 = __expf(trans[j1*T + 2*k]);
            float b1 = __expf(trans[j1*T + 2*k+1]);
            EA[k] = act ? pack2(a0, a1) : 0ull;
            EB[k] = act ? pack2(b0, b1) : 0ull;
        }
    }

    const size_t bbase = (size_t)b * S * T;
    const float* ep0 = emis + bbase + j0;

    const int niter = (!fw && si == 0) ? 358 : 357;
    const int reset = (si == 0) ? -1 : 23;
    const float* ep = fw
        ? ep0 + (size_t)(si == 0 ? 0 : si == 1 ? 333 : 666) * T
        : ep0 - (size_t)(si == 0 ? 0 : si == 1 ? 334 : 667) * T;

    float p0x, p0y;
    if (si != 0) {
        p0x = act ? 1.f : 0.f; p0y = p0x;                     // uniform burn-in
    } else if (fw) {
        float2 e0 = *(const float2*)(ep0);                    // t = 0
        p0x = act ? __expf(startT[j0] + e0.x) : 0.f;
        p0y = act ? __expf(startT[j1] + e0.y) : 0.f;
    } else {
        p0x = act ? __expf(endT[j0]) : 0.f;
        p0y = act ? __expf(endT[j1]) : 0.f;
    }

    float pfx, pfy, cfin;
    if (fw) run_chain<0>(ep, EA, EB, p0x, p0y, niter, reset, l, bufs[w], pfx, pfy, cfin);
    else    run_chain<1>(ep, EA, EB, p0x, p0y, niter, reset, l, bufs[w], pfx, pfy, cfin);

    if (act) {
        if (seg == 2) { g_dir[b][0][2*l] = pfx; g_dir[b][0][2*l+1] = pfy; }
        if (seg == 5) { g_dir[b][1][2*l] = pfx; g_dir[b][1][2*l+1] = pfy; }
    }
    if (l == 0) g_c[b][seg] = cfin;

    // ---- per-warp numerator partial over s in [s0, s1) ----
    const size_t tbase = (size_t)b * S;
    const int s0 = (seg * S) / 6;
    const int s1 = ((seg + 1) * S) / 6;

    // tags dtype detection: int64 iff sampled odd 32-bit words all zero
    int oddw = tagsw[2 * (tbase + s0 + l) + 1];
    const bool is64 = !__any_sync(0xffffffffu, oddw != 0);

    float num = 0.f;
    for (int s = s0 + l; s < s1; s += 32) {
        int cur = is64 ? tagsw[(tbase + s) * 2] : tagsw[tbase + s];
        if (s == 0) {
            num += startT[cur] + emis[bbase + cur];
        } else {
            int prev = is64 ? tagsw[(tbase + s - 1) * 2] : tagsw[tbase + s - 1];
            float m = (float)mask[tbase + s];
            num += (trans[prev*T + cur] + emis[bbase + (size_t)s*T + cur]) * m;
        }
        if (s == S - 1) num += endT[cur];
    }
#pragma unroll
    for (int d = 16; d; d >>= 1) num += __shfl_xor_sync(0xffffffffu, num, d);
    if (l == 0) g_numpart[C] = num;
}

// Kernel 2: tiny combine. grid B x 64 thr.
__global__ void __launch_bounds__(64)
crf_combine(float* __restrict__ out)
{
    __shared__ float shRed[64];
    const int b   = blockIdx.x;
    const int tid = threadIdx.x;

    shRed[tid] = (tid < 48) ? g_dir[b][0][tid] * g_dir[b][1][tid] : 0.f;
    __syncthreads();

    if (tid == 0) {
        float dot = 0.f;
#pragma unroll
        for (int k = 0; k < 48; ++k) dot += shRed[k];
        float cs = 0.f, nm = 0.f;
#pragma unroll
        for (int k = 0; k < 6; ++k) { cs += g_c[b][k]; nm += g_numpart[6*b + k]; }
        out[b] = __logf(dot) + cs - nm;              // NLL
    }
}

extern "C" void kernel_launch(void* const* d_in, const int* in_sizes, int n_in,
                              void* d_out, int out_size) {
    (void)in_sizes; (void)n_in; (void)out_size;
    const float* emis   = (const float*)d_in[0];
    const int*   tagsw  = (const int*)  d_in[1];
    const int*   mask   = (const int*)  d_in[2];
    const float* trans  = (const float*)d_in[3];
    const float* startT = (const float*)d_in[4];
    const float* endT   = (const float*)d_in[5];
    crf_chains <<<296, 192>>>(emis, tagsw, mask, trans, startT, endT);
    crf_combine<<<B, 64>>>((float*)d_out);
}